// round 10
// baseline (speedup 1.0000x reference)
#include <cuda_runtime.h>
#include <cuda_fp16.h>
#include <math.h>
#include <stdint.h>

#define SQ   2048
#define EM   768
#define NH   12
#define DH   64
#define FFD  3072
#define NL   4
#define EPSF 1e-5f
#define NCHUNK 16

// GEMM tiling: BM=128, BN=64, BK=64 halves, 128 threads (2x2 warps, 64x32 warp tile)
// 2-term fp16: A single (rounded), B split hi/lo (exact)
#define BM 128
#define BN 64
#define BK 64
#define RSTR 36            // smem row stride in u32 (32 used + 4 pad)
#define A_OFF 0
#define BH_OFF 4608
#define BL_OFF 6912
#define STAGE_U32 9216
#define SMEM_BYTES (2*STAGE_U32*4)   // 73728 -> 3 CTAs/SM

// weight pool offsets (elements) — Wq,Wk,Wv,W1,W2 (Wo handled via N fusion)
#define WMAT   589824            // 768*768
#define W1MAT  2359296           // 768*3072
#define OFF_WQ 0
#define OFF_WK (4*WMAT)
#define OFF_WV (8*WMAT)
#define OFF_W1 (12*WMAT)
#define OFF_W2 (12*WMAT + 4*W1MAT)
#define WTOTAL (12*WMAT + 8*W1MAT)

// ---------------- scratch (no allocations allowed) ----------------
__device__ float g_x[SQ*EM];                 // residual stream (fp32)
__device__ float g_k[SQ*EM];                 // K (fp32)
__device__ float g_v[SQ*EM];                 // V (fp32)
__device__ float g_Mp[NH*NCHUNK*DH*DH];      // partial K^T V
__device__ float g_part[2*SQ*EM];            // split-K partials (2 splits)
__device__ __half g_qh[SQ*EM];               // Q (fp16)
__device__ __half g_h[SQ*EM];                // LN output (fp16)
__device__ __half g_ff[SQ*FFD];              // MLP hidden (fp16)
__device__ __half gwt_hi[WTOTAL];            // transposed weights hi
__device__ __half gwt_lo[WTOTAL];            // transposed weights lo
__device__ __half g_nh[EM*EM];               // N = scale*M*Wo, transposed, hi
__device__ __half g_nl[EM*EM];               // N lo

// ---------------- helpers ----------------
__device__ __forceinline__ void mma_fp16(float c[4], const uint32_t a[4], const uint32_t b[2]) {
    asm volatile(
        "mma.sync.aligned.m16n8k16.row.col.f32.f16.f16.f32 "
        "{%0,%1,%2,%3},{%4,%5,%6,%7},{%8,%9},{%0,%1,%2,%3};\n"
        : "+f"(c[0]), "+f"(c[1]), "+f"(c[2]), "+f"(c[3])
        : "r"(a[0]), "r"(a[1]), "r"(a[2]), "r"(a[3]), "r"(b[0]), "r"(b[1]));
}
__device__ __forceinline__ void cpa16(uint32_t dst, const void* src) {
    asm volatile("cp.async.cg.shared.global [%0], [%1], 16;\n" :: "r"(dst), "l"(src) : "memory");
}
__device__ __forceinline__ void cp_commit() { asm volatile("cp.async.commit_group;\n" ::: "memory"); }
__device__ __forceinline__ void cp_wait1()  { asm volatile("cp.async.wait_group 1;\n" ::: "memory"); }
__device__ __forceinline__ void cp_wait0()  { asm volatile("cp.async.wait_group 0;\n" ::: "memory"); }

__device__ __forceinline__ void split_fp16(float v, __half& hi, __half& lo) {
    hi = __float2half_rn(v);
    lo = __float2half_rn(v - __half2float(hi));
}

// ---------------- weight transpose + split: src[L][K][N] -> dst[L][N][K] (hi,lo fp16) ----------------
__global__ void wconv_k(const float* __restrict__ src,
                        __half* __restrict__ dhi, __half* __restrict__ dlo,
                        int K, int N) {
    __shared__ float t[32][33];   // t[k_local][n_local]
    const size_t lofs = (size_t)blockIdx.z * K * N;
    const int n0 = blockIdx.x * 32, k0 = blockIdx.y * 32;
    const int tx = threadIdx.x, ty = threadIdx.y;
    #pragma unroll
    for (int i = 0; i < 4; i++)
        t[ty + 8*i][tx] = src[lofs + (size_t)(k0 + ty + 8*i) * N + n0 + tx];
    __syncthreads();
    const int u = tx & 15, nx = tx >> 4;
    #pragma unroll
    for (int i = 0; i < 2; i++) {
        int n = ty + 8*i + 16*nx;
        float v0 = t[2*u][n], v1 = t[2*u + 1][n];
        __half h0, l0, h1, l1;
        split_fp16(v0, h0, l0);
        split_fp16(v1, h1, l1);
        size_t o = lofs + (size_t)(n0 + n) * K + k0 + 2*u;
        *reinterpret_cast<__half2*>(dhi + o) = __halves2half2(h0, h1);
        *reinterpret_cast<__half2*>(dlo + o) = __halves2half2(l0, l1);
    }
}

// ---------------- x = emb + wpe ----------------
__global__ void add_wpe_k(const float* __restrict__ emb, const float* __restrict__ wpe) {
    int i = blockIdx.x * blockDim.x + threadIdx.x;
    if (i < SQ*EM) g_x[i] = emb[i] + wpe[i];
}

// ---------------- layernorm: one block per row; HALF -> fp16, else fp32 ----------------
template<bool HALF>
__global__ void layernorm_k(const float* __restrict__ in, float* __restrict__ outf,
                            __half* __restrict__ oh,
                            const float* __restrict__ g, const float* __restrict__ b) {
    int row = blockIdx.x;
    const float* x = in + row * EM;
    float s = 0.f, s2 = 0.f;
    for (int j = threadIdx.x; j < EM; j += 256) {
        float v = x[j];
        s += v; s2 += v * v;
    }
    __shared__ float rs[32], rs2[32];
    #pragma unroll
    for (int o = 16; o; o >>= 1) {
        s  += __shfl_down_sync(0xffffffffu, s,  o);
        s2 += __shfl_down_sync(0xffffffffu, s2, o);
    }
    int w = threadIdx.x >> 5, l = threadIdx.x & 31;
    if (l == 0) { rs[w] = s; rs2[w] = s2; }
    __syncthreads();
    if (w == 0) {
        s  = (l < 8) ? rs[l]  : 0.f;
        s2 = (l < 8) ? rs2[l] : 0.f;
        #pragma unroll
        for (int o = 4; o; o >>= 1) {
            s  += __shfl_down_sync(0xffffffffu, s,  o);
            s2 += __shfl_down_sync(0xffffffffu, s2, o);
        }
        if (l == 0) { rs[0] = s; rs2[0] = s2; }
    }
    __syncthreads();
    float mu  = rs[0] * (1.0f / EM);
    float var = rs2[0] * (1.0f / EM) - mu * mu;
    float inv = rsqrtf(var + EPSF);
    for (int j = threadIdx.x; j < EM; j += 256) {
        float v = (x[j] - mu) * inv * g[j] + b[j];
        if (HALF) oh[row * EM + j] = __float2half_rn(v);
        else      outf[row * EM + j] = v;
    }
}

// ---------------- combine 2 split-K partials + bias + residual, then LayerNorm ----------------
template<bool HALF>
__global__ void __launch_bounds__(256)
combine_ln_k(const float* __restrict__ parts, const float* __restrict__ bias,
             float* __restrict__ px, float* __restrict__ outf, __half* __restrict__ oh,
             const float* __restrict__ g, const float* __restrict__ b) {
    const int row = blockIdx.x;
    float loc[3];
    float s = 0.f, s2 = 0.f;
    #pragma unroll
    for (int t = 0; t < 3; t++) {
        int j = threadIdx.x + t * 256;
        size_t o = (size_t)row * EM + j;
        float v = px[o] + bias[j] + parts[o] + parts[o + (size_t)SQ*EM];
        px[o] = v;
        loc[t] = v;
        s += v; s2 += v * v;
    }
    __shared__ float rs[32], rs2[32];
    #pragma unroll
    for (int o = 16; o; o >>= 1) {
        s  += __shfl_down_sync(0xffffffffu, s,  o);
        s2 += __shfl_down_sync(0xffffffffu, s2, o);
    }
    int w = threadIdx.x >> 5, l = threadIdx.x & 31;
    if (l == 0) { rs[w] = s; rs2[w] = s2; }
    __syncthreads();
    if (w == 0) {
        s  = (l < 8) ? rs[l]  : 0.f;
        s2 = (l < 8) ? rs2[l] : 0.f;
        #pragma unroll
        for (int o = 4; o; o >>= 1) {
            s  += __shfl_down_sync(0xffffffffu, s,  o);
            s2 += __shfl_down_sync(0xffffffffu, s2, o);
        }
        if (l == 0) { rs[0] = s; rs2[0] = s2; }
    }
    __syncthreads();
    float mu  = rs[0] * (1.0f / EM);
    float var = rs2[0] * (1.0f / EM) - mu * mu;
    float inv = rsqrtf(var + EPSF);
    #pragma unroll
    for (int t = 0; t < 3; t++) {
        int j = threadIdx.x + t * 256;
        float v = (loc[t] - mu) * inv * g[j] + b[j];
        if (HALF) oh[(size_t)row * EM + j] = __float2half_rn(v);
        else      outf[(size_t)row * EM + j] = v;
    }
}

// ---------------- 2-term fp16 tensor-core GEMM body (128x64 tile, 128 threads) ----------------
// A (fp16, [M,Kfull] row-major), B (hi/lo fp16, [N,Kfull] k-major)
template<bool GELU, bool RES, bool OHALF, bool PART>
__device__ __forceinline__ void gemm_body(
    const __half* __restrict__ Ah,
    const __half* __restrict__ Bh, const __half* __restrict__ Bl,
    const float* __restrict__ bias, const float* __restrict__ res,
    float* __restrict__ C, __half* __restrict__ Ch,
    int N, int Kfull, int kbase, int kcount, int row0, int col0, uint32_t* smem)
{
    const int tid  = threadIdx.x;
    const int lane = tid & 31, warp = tid >> 5;
    const int wm = warp >> 1, wn = warp & 1;   // 2 x 2 warp grid, warp tile 64x32
    const int g = lane >> 2, q = lane & 3;

    uint32_t sbase = (uint32_t)__cvta_generic_to_shared(smem);

    float acc[4][4][4];
    #pragma unroll
    for (int i = 0; i < 4; i++)
        #pragma unroll
        for (int j = 0; j < 4; j++)
            #pragma unroll
            for (int t = 0; t < 4; t++) acc[i][j][t] = 0.f;

    const int KT = kcount / BK;

    auto load_tile = [&](int kt, int st) {
        uint32_t base = sbase + st * STAGE_U32 * 4;
        // A: 128 rows x 64 halves = 1024 x 16B chunks
        #pragma unroll
        for (int t = 0; t < 8; t++) {
            int chunk = tid + t * 128;
            int r = chunk >> 3, c4 = (chunk & 7) * 4;
            size_t aoff = (size_t)(row0 + r) * Kfull + kbase + kt * BK + (chunk & 7) * 8;
            cpa16(base + (uint32_t)(A_OFF + r * RSTR + c4) * 4, Ah + aoff);
        }
        // B hi/lo: 64 rows x 64 halves = 512 x 16B chunks each
        #pragma unroll
        for (int t = 0; t < 4; t++) {
            int chunk = tid + t * 128;
            int r = chunk >> 3, c4 = (chunk & 7) * 4;
            size_t boff = (size_t)(col0 + r) * Kfull + kbase + kt * BK + (chunk & 7) * 8;
            cpa16(base + (uint32_t)(BH_OFF + r * RSTR + c4) * 4, Bh + boff);
            cpa16(base + (uint32_t)(BL_OFF + r * RSTR + c4) * 4, Bl + boff);
        }
        cp_commit();
    };

    load_tile(0, 0);
    for (int kt = 0; kt < KT; kt++) {
        if (kt + 1 < KT) { load_tile(kt + 1, (kt + 1) & 1); cp_wait1(); }
        else             { cp_wait0(); }
        __syncthreads();

        const uint32_t* S = smem + (kt & 1) * STAGE_U32;

        #pragma unroll
        for (int ks = 0; ks < 4; ks++) {
            const int kq = ks * 8 + q;
            uint32_t af[4][4], bh[4][2], bl[4][2];
            #pragma unroll
            for (int mi = 0; mi < 4; mi++) {
                int rb = (wm * 64 + mi * 16 + g) * RSTR + kq;
                af[mi][0] = S[A_OFF + rb];       af[mi][1] = S[A_OFF + rb + 8*RSTR];
                af[mi][2] = S[A_OFF + rb + 4];   af[mi][3] = S[A_OFF + rb + 8*RSTR + 4];
            }
            #pragma unroll
            for (int ni = 0; ni < 4; ni++) {
                int nb = (wn * 32 + ni * 8 + g) * RSTR + kq;
                bh[ni][0] = S[BH_OFF + nb];  bh[ni][1] = S[BH_OFF + nb + 4];
                bl[ni][0] = S[BL_OFF + nb];  bl[ni][1] = S[BL_OFF + nb + 4];
            }
            #pragma unroll
            for (int mi = 0; mi < 4; mi++)
                #pragma unroll
                for (int ni = 0; ni < 4; ni++) {
                    mma_fp16(acc[mi][ni], af[mi], bl[ni]);
                    mma_fp16(acc[mi][ni], af[mi], bh[ni]);
                }
        }
        __syncthreads();
    }

    // epilogue (C layout: t0=(g,2q) t1=(g,2q+1) t2=(g+8,2q) t3=(g+8,2q+1))
    #pragma unroll
    for (int mi = 0; mi < 4; mi++) {
        #pragma unroll
        for (int ni = 0; ni < 4; ni++) {
            int r0 = row0 + wm * 64 + mi * 16 + g;
            int c0 = col0 + wn * 32 + ni * 8 + 2 * q;
            float bb0 = PART ? 0.f : bias[c0];
            float bb1 = PART ? 0.f : bias[c0 + 1];
            #pragma unroll
            for (int h = 0; h < 2; h++) {
                int r = r0 + h * 8;
                float v0 = acc[mi][ni][2 * h]     + bb0;
                float v1 = acc[mi][ni][2 * h + 1] + bb1;
                if (GELU) {
                    v0 = 0.5f * v0 * (1.0f + erff(v0 * 0.70710678118654752f));
                    v1 = 0.5f * v1 * (1.0f + erff(v1 * 0.70710678118654752f));
                }
                if (RES) {
                    v0 += res[(size_t)r * N + c0];
                    v1 += res[(size_t)r * N + c0 + 1];
                }
                if (OHALF) {
                    Ch[(size_t)r * N + c0]     = __float2half_rn(v0);
                    Ch[(size_t)r * N + c0 + 1] = __float2half_rn(v1);
                } else {
                    C[(size_t)r * N + c0]     = v0;
                    C[(size_t)r * N + c0 + 1] = v1;
                }
            }
        }
    }
}

template<bool GELU, bool RES, bool OHALF>
__global__ void __launch_bounds__(128, 3)
gemm_tc(const __half* __restrict__ Ah,
        const __half* __restrict__ Bh, const __half* __restrict__ Bl,
        const float* __restrict__ bias, const float* __restrict__ res,
        float* __restrict__ C, __half* __restrict__ Ch, int N, int K) {
    extern __shared__ uint32_t smem[];
    gemm_body<GELU, RES, OHALF, false>(Ah, Bh, Bl, bias, res, C, Ch,
                                       N, K, 0, K, blockIdx.y * BM, blockIdx.x * BN, smem);
}

// split-K partial GEMM: blockIdx.z = split index, writes raw fp32 partials
__global__ void __launch_bounds__(128, 3)
gemm_part_k(const __half* __restrict__ Ah,
            const __half* __restrict__ Bh, const __half* __restrict__ Bl,
            float* __restrict__ parts, int N, int Kfull, int ksplit) {
    extern __shared__ uint32_t smem[];
    float* Cp = parts + (size_t)blockIdx.z * SQ * N;
    gemm_body<false, false, false, true>(Ah, Bh, Bl, nullptr, nullptr, Cp, nullptr,
                                         N, Kfull, blockIdx.z * ksplit, ksplit,
                                         blockIdx.y * BM, blockIdx.x * BN, smem);
}

// fused QKV: grid.x = 3 * (EM/BN); Q -> fp16, K/V -> fp32
__global__ void __launch_bounds__(128, 3)
qkv_tc(const __half* __restrict__ Bq_hi, const __half* __restrict__ Bq_lo,
       const __half* __restrict__ Bk_hi, const __half* __restrict__ Bk_lo,
       const __half* __restrict__ Bv_hi, const __half* __restrict__ Bv_lo,
       const float* __restrict__ bq, const float* __restrict__ bk, const float* __restrict__ bv) {
    extern __shared__ uint32_t smem[];
    const int nb = EM / BN;   // 12
    int m = blockIdx.x / nb, cb = blockIdx.x % nb;
    if (m == 0) {
        gemm_body<false, false, true, false>(g_h, Bq_hi, Bq_lo, bq, nullptr, nullptr, g_qh,
                                             EM, EM, 0, EM, blockIdx.y * BM, cb * BN, smem);
    } else {
        const __half* Bh = (m == 1) ? Bk_hi : Bv_hi;
        const __half* Bl = (m == 1) ? Bk_lo : Bv_lo;
        const float*  b  = (m == 1) ? bk : bv;
        float*        C  = (m == 1) ? g_k : g_v;
        gemm_body<false, false, false, false>(g_h, Bh, Bl, b, nullptr, C, nullptr,
                                              EM, EM, 0, EM, blockIdx.y * BM, cb * BN, smem);
    }
}

// ---------------- attention part 1: partial M = K_h^T V_h over an S-chunk ----------------
__global__ void __launch_bounds__(256) attn_m_k() {
    const int h = blockIdx.x, chunk = blockIdx.y;
    __shared__ float Ks[32][65];
    __shared__ float Vs[32][65];
    const int tid = threadIdx.x;
    const int tx = tid & 15, ty = tid >> 4;
    float acc[4][4] = {};
    const int sbase = chunk * (SQ / NCHUNK);
    for (int s0 = 0; s0 < SQ / NCHUNK; s0 += 32) {
        #pragma unroll
        for (int i = 0; i < 8; i++) {
            int idx = tid + i * 256;
            int r = idx >> 6, c = idx & 63;
            int gidx = (sbase + s0 + r) * EM + h * 64 + c;
            Ks[r][c] = g_k[gidx];
            Vs[r][c] = g_v[gidx];
        }
        __syncthreads();
        #pragma unroll
        for (int ss = 0; ss < 32; ss++) {
            float a[4], bb[4];
            #pragma unroll
            for (int i = 0; i < 4; i++) a[i]  = Ks[ss][ty + i * 16];
            #pragma unroll
            for (int j = 0; j < 4; j++) bb[j] = Vs[ss][tx + j * 16];
            #pragma unroll
            for (int i = 0; i < 4; i++)
                #pragma unroll
                for (int j = 0; j < 4; j++)
                    acc[i][j] += a[i] * bb[j];
        }
        __syncthreads();
    }
    #pragma unroll
    for (int i = 0; i < 4; i++)
        #pragma unroll
        for (int j = 0; j < 4; j++)
            g_Mp[((h * NCHUNK + chunk) * 64 + ty + i * 16) * 64 + tx + j * 16] = acc[i][j];
}

// ---------------- N = scale * M * Wo  (per head, transposed + split fp16) ----------------
__global__ void __launch_bounds__(256) nmat_k(const float* __restrict__ Wo) {
    const int h = blockIdx.x, ob = blockIdx.y;
    __shared__ float Ms[64][65];
    __shared__ float Ws[64][65];
    const int tid = threadIdx.x;
    #pragma unroll
    for (int i = 0; i < 16; i++) {
        int idx = tid + i * 256;
        int d1 = idx >> 6, d2 = idx & 63;
        float s = 0.f;
        #pragma unroll
        for (int c = 0; c < NCHUNK; c++)
            s += g_Mp[((h * NCHUNK + c) * 64 + d1) * 64 + d2];
        Ms[d1][d2] = s * 0.125f;   // DH^-0.5
        int e = idx >> 6, o = idx & 63;
        Ws[e][o] = Wo[(size_t)(h * 64 + e) * EM + ob * 64 + o];
    }
    __syncthreads();
    const int o = tid & 63, dbase = (tid >> 6) * 16;
    #pragma unroll
    for (int dd = 0; dd < 16; dd++) {
        int d = dbase + dd;
        float s = 0.f;
        #pragma unroll
        for (int e = 0; e < 64; e++)
            s += Ms[d][e] * Ws[e][o];
        __half hi, lo;
        split_fp16(s, hi, lo);
        size_t off = (size_t)(ob * 64 + o) * EM + h * 64 + d;
        g_nh[off] = hi;
        g_nl[off] = lo;
    }
}

// ---------------- host ----------------
extern "C" void kernel_launch(void* const* d_in, const int* in_sizes, int n_in,
                              void* d_out, int out_size) {
    const float* emb   = (const float*)d_in[0];
    const float* wpe   = (const float*)d_in[1];
    const float* ln1_g = (const float*)d_in[2];
    const float* ln1_b = (const float*)d_in[3];
    const float* Wq    = (const float*)d_in[4];
    const float* bq    = (const float*)d_in[5];
    const float* Wk    = (const float*)d_in[6];
    const float* bk    = (const float*)d_in[7];
    const float* Wv    = (const float*)d_in[8];
    const float* bv    = (const float*)d_in[9];
    const float* Wo    = (const float*)d_in[10];
    const float* bo    = (const float*)d_in[11];
    const float* ln2_g = (const float*)d_in[12];
    const float* ln2_b = (const float*)d_in[13];
    const float* W1    = (const float*)d_in[14];
    const float* b1    = (const float*)d_in[15];
    const float* W2    = (const float*)d_in[16];
    const float* b2    = (const float*)d_in[17];
    const float* lnf_g = (const float*)d_in[18];
    const float* lnf_b = (const float*)d_in[19];
    float* out = (float*)d_out;

    float *px, *ppart;
    __half *pwh, *pwl, *pnh, *pnl, *pqh, *phh, *pff;
    cudaGetSymbolAddress((void**)&px,    g_x);
    cudaGetSymbolAddress((void**)&ppart, g_part);
    cudaGetSymbolAddress((void**)&pwh,   gwt_hi);
    cudaGetSymbolAddress((void**)&pwl,   gwt_lo);
    cudaGetSymbolAddress((void**)&pnh,   g_nh);
    cudaGetSymbolAddress((void**)&pnl,   g_nl);
    cudaGetSymbolAddress((void**)&pqh,   g_qh);
    cudaGetSymbolAddress((void**)&phh,   g_h);
    cudaGetSymbolAddress((void**)&pff,   g_ff);

    cudaFuncSetAttribute(gemm_tc<true, false, true>,
                         cudaFuncAttributeMaxDynamicSharedMemorySize, SMEM_BYTES);
    cudaFuncSetAttribute(gemm_part_k,
                         cudaFuncAttributeMaxDynamicSharedMemorySize, SMEM_BYTES);
    cudaFuncSetAttribute(qkv_tc,
                         cudaFuncAttributeMaxDynamicSharedMemorySize, SMEM_BYTES);

    // weight transpose + hi/lo split (Wo excluded — fused via N)
    {
        dim3 blk(32, 8);
        wconv_k<<<dim3(EM/32,  EM/32,  NL), blk>>>(Wq, pwh + OFF_WQ, pwl + OFF_WQ, EM,  EM);
        wconv_k<<<dim3(EM/32,  EM/32,  NL), blk>>>(Wk, pwh + OFF_WK, pwl + OFF_WK, EM,  EM);
        wconv_k<<<dim3(EM/32,  EM/32,  NL), blk>>>(Wv, pwh + OFF_WV, pwl + OFF_WV, EM,  EM);
        wconv_k<<<dim3(FFD/32, EM/32,  NL), blk>>>(W1, pwh + OFF_W1, pwl + OFF_W1, EM,  FFD);
        wconv_k<<<dim3(EM/32,  FFD/32, NL), blk>>>(W2, pwh + OFF_W2, pwl + OFF_W2, FFD, EM);
    }

    add_wpe_k<<<(SQ*EM + 255) / 256, 256>>>(emb, wpe);

    const dim3 gQKV(3 * (EM / BN), SQ / BM);     // (36, 16) = 576 CTAs
    const dim3 gS(EM / BN, SQ / BM, 2);          // split-K grids (12, 16, 2) = 384
    const dim3 gF(FFD / BN, SQ / BM);            // (48, 16) = 768

    // initial LN1 (layer 0); subsequent LN1s are fused into W2 combines
    layernorm_k<true><<<SQ, 256>>>(px, nullptr, phh, ln1_g, ln1_b);

    for (int l = 0; l < NL; l++) {
        const __half* wq_h = pwh + OFF_WQ + (size_t)l * WMAT;
        const __half* wq_l = pwl + OFF_WQ + (size_t)l * WMAT;
        const __half* wk_h = pwh + OFF_WK + (size_t)l * WMAT;
        const __half* wk_l = pwl + OFF_WK + (size_t)l * WMAT;
        const __half* wv_h = pwh + OFF_WV + (size_t)l * WMAT;
        const __half* wv_l = pwl + OFF_WV + (size_t)l * WMAT;
        const __half* w1_h = pwh + OFF_W1 + (size_t)l * W1MAT;
        const __half* w1_l = pwl + OFF_W1 + (size_t)l * W1MAT;
        const __half* w2_h = pwh + OFF_W2 + (size_t)l * W1MAT;
        const __half* w2_l = pwl + OFF_W2 + (size_t)l * W1MAT;

        qkv_tc<<<gQKV, 128, SMEM_BYTES>>>(wq_h, wq_l, wk_h, wk_l, wv_h, wv_l,
                                          bq + l * EM, bk + l * EM, bv + l * EM);
        attn_m_k<<<dim3(NH, NCHUNK), 256>>>();
        nmat_k<<<dim3(NH, EM / 64), 256>>>(Wo + (size_t)l * EM * EM);

        // O-projection: split-K=2 (K=768 -> 384 each), combine + LN2 fused
        gemm_part_k<<<gS, 128, SMEM_BYTES>>>(pqh, pnh, pnl, ppart, EM, EM, EM / 2);
        combine_ln_k<true><<<SQ, 256>>>(ppart, bo + l * EM, px, nullptr, phh,
                                        ln2_g + l * EM, ln2_b + l * EM);

        gemm_tc<true, false, true><<<gF, 128, SMEM_BYTES>>>(
            phh, w1_h, w1_l, b1 + l * FFD, nullptr, nullptr, pff, FFD, EM);

        // W2: split-K=2 (K=3072 -> 1536 each), combine + next LN fused
        gemm_part_k<<<gS, 128, SMEM_BYTES>>>(pff, w2_h, w2_l, ppart, EM, FFD, FFD / 2);
        if (l + 1 < NL) {
            combine_ln_k<true><<<SQ, 256>>>(ppart, b2 + l * EM, px, nullptr, phh,
                                            ln1_g + (l + 1) * EM, ln1_b + (l + 1) * EM);
        } else {
            combine_ln_k<false><<<SQ, 256>>>(ppart, b2 + l * EM, px, out, nullptr,
                                             lnf_g, lnf_b);
        }
    }
}

// round 11
// speedup vs baseline: 1.0079x; 1.0079x over previous
#include <cuda_runtime.h>
#include <cuda_fp16.h>
#include <math.h>
#include <stdint.h>

#define SQ   2048
#define EM   768
#define NH   12
#define DH   64
#define FFD  3072
#define NL   4
#define EPSF 1e-5f
#define NCHUNK 32

// GEMM tiling: BM=BN=128, BK=64 halves, 256 threads, warp tile 64x32 (R9 config)
#define BM 128
#define BN 128
#define BK 64
#define RSTR 36            // smem row stride in u32 (32 used + 4 pad)
#define A_OFF 0
#define BH_OFF 4608
#define BL_OFF 9216
#define STAGE_U32 13824
#define SMEM_BYTES (2*STAGE_U32*4)   // 110592

// weight pool offsets (elements) — Wq,Wk,Wv,W1,W2 (Wo handled via N fusion)
#define WMAT   589824            // 768*768
#define W1MAT  2359296           // 768*3072
#define OFF_WQ 0
#define OFF_WK (4*WMAT)
#define OFF_WV (8*WMAT)
#define OFF_W1 (12*WMAT)
#define OFF_W2 (12*WMAT + 4*W1MAT)
#define WTOTAL (12*WMAT + 8*W1MAT)

// ---------------- scratch (no allocations allowed) ----------------
__device__ float g_x[SQ*EM];                 // residual stream (fp32)
__device__ float g_k[SQ*EM];                 // K (fp32)
__device__ float g_v[SQ*EM];                 // V (fp32)
__device__ float g_Mp[NH*NCHUNK*DH*DH];      // partial K^T V
__device__ float g_part[3*SQ*EM];            // split-K partials
__device__ __half g_qh[SQ*EM];               // Q (fp16)
__device__ __half g_h[SQ*EM];                // LN output (fp16)
__device__ __half g_ff[SQ*FFD];              // MLP hidden (fp16)
__device__ __half gwt_hi[WTOTAL];            // transposed weights hi
__device__ __half gwt_lo[WTOTAL];            // transposed weights lo
__device__ __half g_nh[EM*EM];               // N = scale*M*Wo, transposed, hi
__device__ __half g_nl[EM*EM];               // N lo

// ---------------- helpers ----------------
__device__ __forceinline__ void mma_fp16(float c[4], const uint32_t a[4], const uint32_t b[2]) {
    asm volatile(
        "mma.sync.aligned.m16n8k16.row.col.f32.f16.f16.f32 "
        "{%0,%1,%2,%3},{%4,%5,%6,%7},{%8,%9},{%0,%1,%2,%3};\n"
        : "+f"(c[0]), "+f"(c[1]), "+f"(c[2]), "+f"(c[3])
        : "r"(a[0]), "r"(a[1]), "r"(a[2]), "r"(a[3]), "r"(b[0]), "r"(b[1]));
}
__device__ __forceinline__ void cpa16(uint32_t dst, const void* src) {
    asm volatile("cp.async.cg.shared.global [%0], [%1], 16;\n" :: "r"(dst), "l"(src) : "memory");
}
__device__ __forceinline__ void cp_commit() { asm volatile("cp.async.commit_group;\n" ::: "memory"); }
__device__ __forceinline__ void cp_wait1()  { asm volatile("cp.async.wait_group 1;\n" ::: "memory"); }
__device__ __forceinline__ void cp_wait0()  { asm volatile("cp.async.wait_group 0;\n" ::: "memory"); }

__device__ __forceinline__ void split_fp16(float v, __half& hi, __half& lo) {
    hi = __float2half_rn(v);
    lo = __float2half_rn(v - __half2float(hi));
}

// ---------------- weight transpose + split: src[L][K][N] -> dst[L][N][K] (hi,lo fp16) ----------------
// QKV=true: grid.z in [0, 3*NL), selects among 3 source matrices
template<bool QKV>
__global__ void wconv_k(const float* __restrict__ s0, const float* __restrict__ s1,
                        const float* __restrict__ s2,
                        __half* __restrict__ dhi, __half* __restrict__ dlo,
                        int K, int N, int poolStride) {
    __shared__ float t[32][33];   // t[k_local][n_local]
    int m = 0, l = blockIdx.z;
    if (QKV) { m = blockIdx.z / NL; l = blockIdx.z % NL; }
    const float* src = (m == 0) ? s0 : (m == 1) ? s1 : s2;
    const size_t lofs = (size_t)l * K * N;
    const size_t dofs = (size_t)m * 4 * WMAT + (size_t)l * poolStride;
    const int n0 = blockIdx.x * 32, k0 = blockIdx.y * 32;
    const int tx = threadIdx.x, ty = threadIdx.y;
    #pragma unroll
    for (int i = 0; i < 4; i++)
        t[ty + 8*i][tx] = src[lofs + (size_t)(k0 + ty + 8*i) * N + n0 + tx];
    __syncthreads();
    const int u = tx & 15, nx = tx >> 4;
    #pragma unroll
    for (int i = 0; i < 2; i++) {
        int n = ty + 8*i + 16*nx;
        float v0 = t[2*u][n], v1 = t[2*u + 1][n];
        __half h0, l0, h1, l1;
        split_fp16(v0, h0, l0);
        split_fp16(v1, h1, l1);
        size_t o = dofs + (size_t)(n0 + n) * K + k0 + 2*u;
        *reinterpret_cast<__half2*>(dhi + o) = __halves2half2(h0, h1);
        *reinterpret_cast<__half2*>(dlo + o) = __halves2half2(l0, l1);
    }
}

// ---------------- initial: x = emb + wpe, then LN -> fp16 ----------------
__global__ void __launch_bounds__(256)
addln_k(const float* __restrict__ emb, const float* __restrict__ wpe,
        float* __restrict__ px, __half* __restrict__ oh,
        const float* __restrict__ g, const float* __restrict__ b) {
    const int row = blockIdx.x;
    float loc[3];
    float s = 0.f, s2 = 0.f;
    #pragma unroll
    for (int t = 0; t < 3; t++) {
        int j = threadIdx.x + t * 256;
        size_t o = (size_t)row * EM + j;
        float v = emb[o] + wpe[o];
        px[o] = v;
        loc[t] = v;
        s += v; s2 += v * v;
    }
    __shared__ float rs[32], rs2[32];
    #pragma unroll
    for (int o = 16; o; o >>= 1) {
        s  += __shfl_down_sync(0xffffffffu, s,  o);
        s2 += __shfl_down_sync(0xffffffffu, s2, o);
    }
    int w = threadIdx.x >> 5, l = threadIdx.x & 31;
    if (l == 0) { rs[w] = s; rs2[w] = s2; }
    __syncthreads();
    if (w == 0) {
        s  = (l < 8) ? rs[l]  : 0.f;
        s2 = (l < 8) ? rs2[l] : 0.f;
        #pragma unroll
        for (int o = 4; o; o >>= 1) {
            s  += __shfl_down_sync(0xffffffffu, s,  o);
            s2 += __shfl_down_sync(0xffffffffu, s2, o);
        }
        if (l == 0) { rs[0] = s; rs2[0] = s2; }
    }
    __syncthreads();
    float mu  = rs[0] * (1.0f / EM);
    float var = rs2[0] * (1.0f / EM) - mu * mu;
    float inv = rsqrtf(var + EPSF);
    #pragma unroll
    for (int t = 0; t < 3; t++) {
        int j = threadIdx.x + t * 256;
        oh[(size_t)row * EM + j] = __float2half_rn((loc[t] - mu) * inv * g[j] + b[j]);
    }
}

// ---------------- combine 3 split-K partials + bias + residual, then LayerNorm ----------------
template<bool HALF>
__global__ void __launch_bounds__(256)
combine_ln_k(const float* __restrict__ parts, const float* __restrict__ bias,
             float* __restrict__ px, float* __restrict__ outf, __half* __restrict__ oh,
             const float* __restrict__ g, const float* __restrict__ b) {
    const int row = blockIdx.x;
    float loc[3];
    float s = 0.f, s2 = 0.f;
    #pragma unroll
    for (int t = 0; t < 3; t++) {
        int j = threadIdx.x + t * 256;
        size_t o = (size_t)row * EM + j;
        float v = px[o] + bias[j] + parts[o] + parts[o + (size_t)SQ*EM] + parts[o + 2*(size_t)SQ*EM];
        px[o] = v;
        loc[t] = v;
        s += v; s2 += v * v;
    }
    __shared__ float rs[32], rs2[32];
    #pragma unroll
    for (int o = 16; o; o >>= 1) {
        s  += __shfl_down_sync(0xffffffffu, s,  o);
        s2 += __shfl_down_sync(0xffffffffu, s2, o);
    }
    int w = threadIdx.x >> 5, l = threadIdx.x & 31;
    if (l == 0) { rs[w] = s; rs2[w] = s2; }
    __syncthreads();
    if (w == 0) {
        s  = (l < 8) ? rs[l]  : 0.f;
        s2 = (l < 8) ? rs2[l] : 0.f;
        #pragma unroll
        for (int o = 4; o; o >>= 1) {
            s  += __shfl_down_sync(0xffffffffu, s,  o);
            s2 += __shfl_down_sync(0xffffffffu, s2, o);
        }
        if (l == 0) { rs[0] = s; rs2[0] = s2; }
    }
    __syncthreads();
    float mu  = rs[0] * (1.0f / EM);
    float var = rs2[0] * (1.0f / EM) - mu * mu;
    float inv = rsqrtf(var + EPSF);
    #pragma unroll
    for (int t = 0; t < 3; t++) {
        int j = threadIdx.x + t * 256;
        float v = (loc[t] - mu) * inv * g[j] + b[j];
        if (HALF) oh[(size_t)row * EM + j] = __float2half_rn(v);
        else      outf[(size_t)row * EM + j] = v;
    }
}

// ---------------- 2-term fp16 tensor-core GEMM body (BK=64, 128x128) ----------------
// A (fp16, [M,Kfull] row-major), B (hi/lo fp16, [N,Kfull] k-major)
template<bool GELU, bool RES, bool OHALF, bool PART>
__device__ __forceinline__ void gemm_body(
    const __half* __restrict__ Ah,
    const __half* __restrict__ Bh, const __half* __restrict__ Bl,
    const float* __restrict__ bias, const float* __restrict__ res,
    float* __restrict__ C, __half* __restrict__ Ch,
    int N, int Kfull, int kbase, int kcount, int row0, int col0, uint32_t* smem)
{
    const int tid  = threadIdx.x;
    const int lane = tid & 31, warp = tid >> 5;
    const int wm = warp >> 2, wn = warp & 3;   // 2 x 4 warp grid
    const int g = lane >> 2, q = lane & 3;

    uint32_t sbase = (uint32_t)__cvta_generic_to_shared(smem);

    float acc[4][4][4];
    #pragma unroll
    for (int i = 0; i < 4; i++)
        #pragma unroll
        for (int j = 0; j < 4; j++)
            #pragma unroll
            for (int t = 0; t < 4; t++) acc[i][j][t] = 0.f;

    const int KT = kcount / BK;

    auto load_tile = [&](int kt, int st) {
        uint32_t base = sbase + st * STAGE_U32 * 4;
        #pragma unroll
        for (int t = 0; t < 4; t++) {
            int chunk = tid + t * 256;             // 0..1023
            int r = chunk >> 3, c4 = (chunk & 7) * 4;
            size_t aoff = (size_t)(row0 + r) * Kfull + kbase + kt * BK + (chunk & 7) * 8;
            cpa16(base + (uint32_t)(A_OFF + r * RSTR + c4) * 4, Ah + aoff);
            size_t boff = (size_t)(col0 + r) * Kfull + kbase + kt * BK + (chunk & 7) * 8;
            cpa16(base + (uint32_t)(BH_OFF + r * RSTR + c4) * 4, Bh + boff);
            cpa16(base + (uint32_t)(BL_OFF + r * RSTR + c4) * 4, Bl + boff);
        }
        cp_commit();
    };

    load_tile(0, 0);
    for (int kt = 0; kt < KT; kt++) {
        if (kt + 1 < KT) { load_tile(kt + 1, (kt + 1) & 1); cp_wait1(); }
        else             { cp_wait0(); }
        __syncthreads();

        const uint32_t* S = smem + (kt & 1) * STAGE_U32;

        #pragma unroll
        for (int ks = 0; ks < 4; ks++) {
            const int kq = ks * 8 + q;
            uint32_t af[4][4], bh[4][2], bl[4][2];
            #pragma unroll
            for (int mi = 0; mi < 4; mi++) {
                int rb = (wm * 64 + mi * 16 + g) * RSTR + kq;
                af[mi][0] = S[A_OFF + rb];       af[mi][1] = S[A_OFF + rb + 8*RSTR];
                af[mi][2] = S[A_OFF + rb + 4];   af[mi][3] = S[A_OFF + rb + 8*RSTR + 4];
            }
            #pragma unroll
            for (int ni = 0; ni < 4; ni++) {
                int nb = (wn * 32 + ni * 8 + g) * RSTR + kq;
                bh[ni][0] = S[BH_OFF + nb];  bh[ni][1] = S[BH_OFF + nb + 4];
                bl[ni][0] = S[BL_OFF + nb];  bl[ni][1] = S[BL_OFF + nb + 4];
            }
            #pragma unroll
            for (int mi = 0; mi < 4; mi++)
                #pragma unroll
                for (int ni = 0; ni < 4; ni++) {
                    mma_fp16(acc[mi][ni], af[mi], bl[ni]);
                    mma_fp16(acc[mi][ni], af[mi], bh[ni]);
                }
        }
        __syncthreads();
    }

    // epilogue (C layout: t0=(g,2q) t1=(g,2q+1) t2=(g+8,2q) t3=(g+8,2q+1))
    #pragma unroll
    for (int mi = 0; mi < 4; mi++) {
        #pragma unroll
        for (int ni = 0; ni < 4; ni++) {
            int r0 = row0 + wm * 64 + mi * 16 + g;
            int c0 = col0 + wn * 32 + ni * 8 + 2 * q;
            float bb0 = PART ? 0.f : bias[c0];
            float bb1 = PART ? 0.f : bias[c0 + 1];
            #pragma unroll
            for (int h = 0; h < 2; h++) {
                int r = r0 + h * 8;
                float v0 = acc[mi][ni][2 * h]     + bb0;
                float v1 = acc[mi][ni][2 * h + 1] + bb1;
                if (GELU) {
                    v0 = 0.5f * v0 * (1.0f + erff(v0 * 0.70710678118654752f));
                    v1 = 0.5f * v1 * (1.0f + erff(v1 * 0.70710678118654752f));
                }
                if (RES) {
                    v0 += res[(size_t)r * N + c0];
                    v1 += res[(size_t)r * N + c0 + 1];
                }
                if (OHALF) {
                    Ch[(size_t)r * N + c0]     = __float2half_rn(v0);
                    Ch[(size_t)r * N + c0 + 1] = __float2half_rn(v1);
                } else {
                    C[(size_t)r * N + c0]     = v0;
                    C[(size_t)r * N + c0 + 1] = v1;
                }
            }
        }
    }
}

template<bool GELU, bool RES, bool OHALF>
__global__ void __launch_bounds__(256, 2)
gemm_tc(const __half* __restrict__ Ah,
        const __half* __restrict__ Bh, const __half* __restrict__ Bl,
        const float* __restrict__ bias, const float* __restrict__ res,
        float* __restrict__ C, __half* __restrict__ Ch, int N, int K) {
    extern __shared__ uint32_t smem[];
    gemm_body<GELU, RES, OHALF, false>(Ah, Bh, Bl, bias, res, C, Ch,
                                       N, K, 0, K, blockIdx.y * BM, blockIdx.x * BN, smem);
}

// split-K partial GEMM: blockIdx.z = split index, writes raw fp32 partials
__global__ void __launch_bounds__(256, 2)
gemm_part_k(const __half* __restrict__ Ah,
            const __half* __restrict__ Bh, const __half* __restrict__ Bl,
            float* __restrict__ parts, int N, int Kfull, int ksplit) {
    extern __shared__ uint32_t smem[];
    float* Cp = parts + (size_t)blockIdx.z * SQ * N;
    gemm_body<false, false, false, true>(Ah, Bh, Bl, nullptr, nullptr, Cp, nullptr,
                                         N, Kfull, blockIdx.z * ksplit, ksplit,
                                         blockIdx.y * BM, blockIdx.x * BN, smem);
}

// fused QKV: grid.x = 3 * (EM/BN); Q -> fp16, K/V -> fp32
__global__ void __launch_bounds__(256, 2)
qkv_tc(const __half* __restrict__ Bq_hi, const __half* __restrict__ Bq_lo,
       const __half* __restrict__ Bk_hi, const __half* __restrict__ Bk_lo,
       const __half* __restrict__ Bv_hi, const __half* __restrict__ Bv_lo,
       const float* __restrict__ bq, const float* __restrict__ bk, const float* __restrict__ bv) {
    extern __shared__ uint32_t smem[];
    const int nb = EM / BN;   // 6
    int m = blockIdx.x / nb, cb = blockIdx.x % nb;
    if (m == 0) {
        gemm_body<false, false, true, false>(g_h, Bq_hi, Bq_lo, bq, nullptr, nullptr, g_qh,
                                             EM, EM, 0, EM, blockIdx.y * BM, cb * BN, smem);
    } else {
        const __half* Bh = (m == 1) ? Bk_hi : Bv_hi;
        const __half* Bl = (m == 1) ? Bk_lo : Bv_lo;
        const float*  b  = (m == 1) ? bk : bv;
        float*        C  = (m == 1) ? g_k : g_v;
        gemm_body<false, false, false, false>(g_h, Bh, Bl, b, nullptr, C, nullptr,
                                              EM, EM, 0, EM, blockIdx.y * BM, cb * BN, smem);
    }
}

// ---------------- attention part 1: partial M = K_h^T V_h over an S-chunk ----------------
__global__ void __launch_bounds__(256) attn_m_k() {
    const int h = blockIdx.x, chunk = blockIdx.y;
    __shared__ float Ks[32][65];
    __shared__ float Vs[32][65];
    const int tid = threadIdx.x;
    const int tx = tid & 15, ty = tid >> 4;
    float acc[4][4] = {};
    const int sbase = chunk * (SQ / NCHUNK);
    for (int s0 = 0; s0 < SQ / NCHUNK; s0 += 32) {
        #pragma unroll
        for (int i = 0; i < 8; i++) {
            int idx = tid + i * 256;
            int r = idx >> 6, c = idx & 63;
            int gidx = (sbase + s0 + r) * EM + h * 64 + c;
            Ks[r][c] = g_k[gidx];
            Vs[r][c] = g_v[gidx];
        }
        __syncthreads();
        #pragma unroll
        for (int ss = 0; ss < 32; ss++) {
            float a[4], bb[4];
            #pragma unroll
            for (int i = 0; i < 4; i++) a[i]  = Ks[ss][ty + i * 16];
            #pragma unroll
            for (int j = 0; j < 4; j++) bb[j] = Vs[ss][tx + j * 16];
            #pragma unroll
            for (int i = 0; i < 4; i++)
                #pragma unroll
                for (int j = 0; j < 4; j++)
                    acc[i][j] += a[i] * bb[j];
        }
        __syncthreads();
    }
    #pragma unroll
    for (int i = 0; i < 4; i++)
        #pragma unroll
        for (int j = 0; j < 4; j++)
            g_Mp[((h * NCHUNK + chunk) * 64 + ty + i * 16) * 64 + tx + j * 16] = acc[i][j];
}

// ---------------- N = scale * M * Wo  (per head, transposed + split fp16) ----------------
__global__ void __launch_bounds__(256) nmat_k(const float* __restrict__ Wo) {
    const int h = blockIdx.x, ob = blockIdx.y;
    __shared__ float Ms[64][65];
    __shared__ float Ws[64][65];
    const int tid = threadIdx.x;
    #pragma unroll
    for (int i = 0; i < 16; i++) {
        int idx = tid + i * 256;
        int d1 = idx >> 6, d2 = idx & 63;
        float s = 0.f;
        #pragma unroll
        for (int c = 0; c < NCHUNK; c++)
            s += g_Mp[((h * NCHUNK + c) * 64 + d1) * 64 + d2];
        Ms[d1][d2] = s * 0.125f;   // DH^-0.5
        int e = idx >> 6, o = idx & 63;
        Ws[e][o] = Wo[(size_t)(h * 64 + e) * EM + ob * 64 + o];
    }
    __syncthreads();
    const int o = tid & 63, dbase = (tid >> 6) * 16;
    #pragma unroll
    for (int dd = 0; dd < 16; dd++) {
        int d = dbase + dd;
        float s = 0.f;
        #pragma unroll
        for (int e = 0; e < 64; e++)
            s += Ms[d][e] * Ws[e][o];
        __half hi, lo;
        split_fp16(s, hi, lo);
        size_t off = (size_t)(ob * 64 + o) * EM + h * 64 + d;
        g_nh[off] = hi;
        g_nl[off] = lo;
    }
}

// ---------------- host ----------------
extern "C" void kernel_launch(void* const* d_in, const int* in_sizes, int n_in,
                              void* d_out, int out_size) {
    const float* emb   = (const float*)d_in[0];
    const float* wpe   = (const float*)d_in[1];
    const float* ln1_g = (const float*)d_in[2];
    const float* ln1_b = (const float*)d_in[3];
    const float* Wq    = (const float*)d_in[4];
    const float* bq    = (const float*)d_in[5];
    const float* Wk    = (const float*)d_in[6];
    const float* bk    = (const float*)d_in[7];
    const float* Wv    = (const float*)d_in[8];
    const float* bv    = (const float*)d_in[9];
    const float* Wo    = (const float*)d_in[10];
    const float* bo    = (const float*)d_in[11];
    const float* ln2_g = (const float*)d_in[12];
    const float* ln2_b = (const float*)d_in[13];
    const float* W1    = (const float*)d_in[14];
    const float* b1    = (const float*)d_in[15];
    const float* W2    = (const float*)d_in[16];
    const float* b2    = (const float*)d_in[17];
    const float* lnf_g = (const float*)d_in[18];
    const float* lnf_b = (const float*)d_in[19];
    float* out = (float*)d_out;

    float *px, *ppart;
    __half *pwh, *pwl, *pnh, *pnl, *pqh, *phh, *pff;
    cudaGetSymbolAddress((void**)&px,    g_x);
    cudaGetSymbolAddress((void**)&ppart, g_part);
    cudaGetSymbolAddress((void**)&pwh,   gwt_hi);
    cudaGetSymbolAddress((void**)&pwl,   gwt_lo);
    cudaGetSymbolAddress((void**)&pnh,   g_nh);
    cudaGetSymbolAddress((void**)&pnl,   g_nl);
    cudaGetSymbolAddress((void**)&pqh,   g_qh);
    cudaGetSymbolAddress((void**)&phh,   g_h);
    cudaGetSymbolAddress((void**)&pff,   g_ff);

    cudaFuncSetAttribute(gemm_tc<true, false, true>,
                         cudaFuncAttributeMaxDynamicSharedMemorySize, SMEM_BYTES);
    cudaFuncSetAttribute(gemm_part_k,
                         cudaFuncAttributeMaxDynamicSharedMemorySize, SMEM_BYTES);
    cudaFuncSetAttribute(qkv_tc,
                         cudaFuncAttributeMaxDynamicSharedMemorySize, SMEM_BYTES);

    // weight transpose + hi/lo split (Wo excluded — fused via N)
    {
        dim3 blk(32, 8);
        // Wq, Wk, Wv in one launch (grid.z = 3*NL)
        wconv_k<true><<<dim3(EM/32, EM/32, 3*NL), blk>>>(
            Wq, Wk, Wv, pwh + OFF_WQ, pwl + OFF_WQ, EM, EM, WMAT);
        wconv_k<false><<<dim3(FFD/32, EM/32,  NL), blk>>>(
            W1, nullptr, nullptr, pwh + OFF_W1, pwl + OFF_W1, EM,  FFD, W1MAT);
        wconv_k<false><<<dim3(EM/32,  FFD/32, NL), blk>>>(
            W2, nullptr, nullptr, pwh + OFF_W2, pwl + OFF_W2, FFD, EM,  W1MAT);
    }

    const dim3 gQKV(3 * (EM / BN), SQ / BM);     // (18, 16)
    const dim3 gS(EM / BN, SQ / BM, 3);          // split-K grids (6, 16, 3)
    const dim3 gF(FFD / BN, SQ / BM);            // (24, 16)

    // x = emb + wpe fused with LN1 (layer 0)
    addln_k<<<SQ, 256>>>(emb, wpe, px, phh, ln1_g, ln1_b);

    for (int l = 0; l < NL; l++) {
        const __half* wq_h = pwh + OFF_WQ + (size_t)l * WMAT;
        const __half* wq_l = pwl + OFF_WQ + (size_t)l * WMAT;
        const __half* wk_h = pwh + OFF_WK + (size_t)l * WMAT;
        const __half* wk_l = pwl + OFF_WK + (size_t)l * WMAT;
        const __half* wv_h = pwh + OFF_WV + (size_t)l * WMAT;
        const __half* wv_l = pwl + OFF_WV + (size_t)l * WMAT;
        const __half* w1_h = pwh + OFF_W1 + (size_t)l * W1MAT;
        const __half* w1_l = pwl + OFF_W1 + (size_t)l * W1MAT;
        const __half* w2_h = pwh + OFF_W2 + (size_t)l * W1MAT;
        const __half* w2_l = pwl + OFF_W2 + (size_t)l * W1MAT;

        qkv_tc<<<gQKV, 256, SMEM_BYTES>>>(wq_h, wq_l, wk_h, wk_l, wv_h, wv_l,
                                          bq + l * EM, bk + l * EM, bv + l * EM);
        attn_m_k<<<dim3(NH, NCHUNK), 256>>>();
        nmat_k<<<dim3(NH, EM / 64), 256>>>(Wo + (size_t)l * EM * EM);

        // O-projection: split-K=3 (K=768 -> 256 each), combine + LN2 fused
        gemm_part_k<<<gS, 256, SMEM_BYTES>>>(pqh, pnh, pnl, ppart, EM, EM, EM / 3);
        combine_ln_k<true><<<SQ, 256>>>(ppart, bo + l * EM, px, nullptr, phh,
                                        ln2_g + l * EM, ln2_b + l * EM);

        gemm_tc<true, false, true><<<gF, 256, SMEM_BYTES>>>(
            phh, w1_h, w1_l, b1 + l * FFD, nullptr, nullptr, pff, FFD, EM);

        // W2: split-K=3 (K=3072 -> 1024 each), combine + next LN fused
        gemm_part_k<<<gS, 256, SMEM_BYTES>>>(pff, w2_h, w2_l, ppart, EM, FFD, FFD / 3);
        if (l + 1 < NL) {
            combine_ln_k<true><<<SQ, 256>>>(ppart, b2 + l * EM, px, nullptr, phh,
                                            ln1_g + (l + 1) * EM, ln1_b + (l + 1) * EM);
        } else {
            combine_ln_k<false><<<SQ, 256>>>(ppart, b2 + l * EM, px, out, nullptr,
                                             lnf_g, lnf_b);
        }
    }
}